// round 3
// baseline (speedup 1.0000x reference)
#include <cuda_runtime.h>
#include <cstdint>
#include <cmath>

// HDCProcessor: bit-domain exponential-decay scan, exact 3-phase form.
//   hdc[t,d] = 0.3*s(t,d) + 0.7*s(t,d)*s(t-1,d-1)*s(t-2,d-2)  (signs, rolls mod D)
//   acc_t = 0.95*acc_{t-1} + hdc_t ;  out[t] = acc_t * (1-g)/(1-g^{t+1})
// Phase 1: per-chunk partial sums (zero-init recursion, no stores in loop).
// Phase 2: scan of 32 per-chunk carries: A[c] = partial[c] + g^64 * A[c-1].
// Phase 3: re-run each chunk seeded with its exact carry, storing every step.
// Every timestep is processed exactly twice; result is exact (no truncation).

#define DDIM     4096
#define NB       8
#define NT       2048
#define NCHUNK   32
#define CLEN     64
#define NTHREADS 128
#define NDG      8                 // 4096 dims / (128 thr * 4 dims)
#define ROWW     17                // words per staged row: 1 halo + 16 slice
#define RWORDS   (256 * ROWW)      // 4352
#define ROWB     (ROWW * 4)        // staged row stride in bytes

__device__ uint32_t g_bitsx[NDG * RWORDS];          // per-dg pre-halo'd packed rows
__device__ float    g_inv[NT];                      // (1-g)/(1-g^{t+1})
__device__ float    g_partial[NB * NCHUNK * DDIM];
__device__ float    g_carry[NB * NCHUNK * DDIM];

// ---- pack: sign bits of the bipolar codebook, expanded per d-group ----
__global__ void pack_kernel(const float* __restrict__ cb) {
    const int row  = blockIdx.x;
    const int lane = threadIdx.x & 31;
    const int w0   = threadIdx.x >> 5;
    for (int gw = w0; gw < 128; gw += 4) {
        float v = cb[row * DDIM + gw * 32 + lane];
        unsigned m = __ballot_sync(0xffffffffu, v < 0.0f);
        if (lane == 0) {
            g_bitsx[(gw >> 4) * RWORDS + row * ROWW + (gw & 15) + 1] = m;
            int gwn = (gw + 1) & 127;               // this word is the halo of
            if ((gwn & 15) == 0)                    // the next d-group (mod wrap)
                g_bitsx[(gwn >> 4) * RWORDS + row * ROWW] = m;
        }
    }
    int gid = blockIdx.x * NTHREADS + threadIdx.x;
    if (gid < NT)
        g_inv[gid] = (float)(0.05 / (1.0 - pow(0.95, (double)(gid + 1))));
}

// ---- phase 2: carry scan over chunks ----
__global__ void carry_kernel(float g64) {
    const int gid = blockIdx.x * blockDim.x + threadIdx.x;  // 0 .. NB*DDIM/4-1
    const int b   = gid >> 10;                              // DDIM/4 = 1024
    const int d4  = gid & 1023;
    const float4* pp = (const float4*)g_partial + (size_t)b * NCHUNK * (DDIM / 4) + d4;
    float4*       cp = (float4*)g_carry        + (size_t)b * NCHUNK * (DDIM / 4) + d4;
    float4 a = make_float4(0.f, 0.f, 0.f, 0.f);
#pragma unroll
    for (int c = 0; c < NCHUNK; c++) {
        cp[c * (DDIM / 4)] = a;                    // carry[c] = A[c-1]
        float4 p = pp[c * (DDIM / 4)];
        a.x = fmaf(g64, a.x, p.x);
        a.y = fmaf(g64, a.y, p.y);
        a.z = fmaf(g64, a.z, p.z);
        a.w = fmaf(g64, a.w, p.w);
    }
}

// ---- phases 1 & 3 ----
template <bool FINAL>
__global__ void __launch_bounds__(NTHREADS)
scan_kernel(const int* __restrict__ idx, float* __restrict__ out)
{
    const int dg    = blockIdx.x;
    const int chunk = blockIdx.y;
    const int b     = blockIdx.z;
    const int t0    = chunk * CLEN;
    const int tid   = threadIdx.x;

    __shared__ uint32_t s_bits[RWORDS + 4];
    __shared__ int      s_idx[CLEN + 2];       // pre-scaled row byte offsets
    __shared__ float    s_inv[CLEN];

    // stage packed slice (contiguous uint4 copy)
    {
        const uint4* src = (const uint4*)(g_bitsx + dg * RWORDS);
        uint4*       dst = (uint4*)s_bits;
        for (int k = tid; k < RWORDS / 4; k += NTHREADS) dst[k] = src[k];
    }
    // stage idx[b, t0-2 .. t0+CLEN-1] as byte offsets (t<0 padded, never used)
    if (tid < CLEN + 2) {
        int t = t0 - 2 + tid;
        s_idx[tid] = (t >= 0 ? idx[b * NT + t] : 0) * ROWB;
    }
    if (FINAL && tid < CLEN) s_inv[tid] = g_inv[t0 + tid];
    __syncthreads();

    // bit field: global dim (dg*512 + m) lives at staged-row bit (32 + m);
    // this thread needs dims d-2 .. d+3 => bits starting at p = 30 + 4*tid.
    const int p   = 30 + 4 * tid;
    const int q   = p >> 5;
    const int rsh = p & 31;
    const char* bbase = (const char*)(s_bits + q);

    uint32_t h1s = 0, h2s = 0;   // histories pre-shifted: f_{t-1}<<1, f_{t-2}<<2
    if (chunk) {
        const uint32_t* w1 = (const uint32_t*)(bbase + s_idx[1]);
        const uint32_t* w2 = (const uint32_t*)(bbase + s_idx[0]);
        h1s = __funnelshift_r(w1[0], w1[1], rsh) << 1;
        h2s = __funnelshift_r(w2[0], w2[1], rsh) << 2;
    }

    float a0, a1, a2, a3;
    float* op = nullptr;
    if (FINAL) {
        const float4 cv = *(const float4*)(g_carry +
            ((size_t)(b * NCHUNK + chunk) * DDIM) + dg * 512 + 4 * tid);
        a0 = cv.x; a1 = cv.y; a2 = cv.z; a3 = cv.w;
        op = out + ((size_t)b * NT + t0) * DDIM + dg * 512 + 4 * tid;
    } else {
        a0 = a1 = a2 = a3 = 0.f;
    }

    // one scan step: u_j = cur sign (+-0.3 direct), v_j = trigram sign (+-1),
    // c = W*v + u ; acc = 0.95*acc + c  (0.95 immediate-form FFMA)
#define STEP(s, W)                                                            \
    {                                                                         \
        const uint32_t* wp = (const uint32_t*)(bbase + s_idx[(s) + 2]);       \
        const uint32_t f = __funnelshift_r(wp[0], wp[1], rsh);                \
        const uint32_t Y = f ^ h1s ^ h2s;                                     \
        {                                                                     \
            uint32_t ub, vb; float c;                                         \
            ub = ((f << 29) & 0x80000000u) | 0x3E99999Au;                     \
            vb = ((Y << 29) & 0x80000000u) | 0x3F800000u;                     \
            c  = fmaf((W), __uint_as_float(vb), __uint_as_float(ub));         \
            a0 = fmaf(0.95f, a0, c);                                          \
            ub = ((f << 28) & 0x80000000u) | 0x3E99999Au;                     \
            vb = ((Y << 28) & 0x80000000u) | 0x3F800000u;                     \
            c  = fmaf((W), __uint_as_float(vb), __uint_as_float(ub));         \
            a1 = fmaf(0.95f, a1, c);                                          \
            ub = ((f << 27) & 0x80000000u) | 0x3E99999Au;                     \
            vb = ((Y << 27) & 0x80000000u) | 0x3F800000u;                     \
            c  = fmaf((W), __uint_as_float(vb), __uint_as_float(ub));         \
            a2 = fmaf(0.95f, a2, c);                                          \
            ub = ((f << 26) & 0x80000000u) | 0x3E99999Au;                     \
            vb = ((Y << 26) & 0x80000000u) | 0x3F800000u;                     \
            c  = fmaf((W), __uint_as_float(vb), __uint_as_float(ub));         \
            a3 = fmaf(0.95f, a3, c);                                          \
        }                                                                     \
        if (FINAL) {                                                          \
            const float inv = s_inv[(s)];                                     \
            *(float4*)op = make_float4(a0 * inv, a1 * inv, a2 * inv, a3 * inv);\
            op += DDIM;                                                       \
        }                                                                     \
        h2s = h1s << 1;                                                       \
        h1s = f << 1;                                                         \
    }

    if (chunk == 0) {
        // t = 0,1: reference zeroes the shifted-history rows -> trigram = 0
        STEP(0, 0.0f)
        STEP(1, 0.0f)
#pragma unroll 4
        for (int s = 2; s < CLEN; s++) STEP(s, 0.7f)
    } else {
#pragma unroll 4
        for (int s = 0; s < CLEN; s++) STEP(s, 0.7f)
    }
#undef STEP

    if (!FINAL) {
        *(float4*)(g_partial + ((size_t)(b * NCHUNK + chunk) * DDIM)
                   + dg * 512 + 4 * tid) = make_float4(a0, a1, a2, a3);
    }
}

extern "C" void kernel_launch(void* const* d_in, const int* in_sizes, int n_in,
                              void* d_out, int out_size)
{
    const float* cb  = (const float*)d_in[0];   // (256, 4096) f32 bipolar
    const int*   idx = (const int*)d_in[1];     // (8, 2048) i32
    float*       out = (float*)d_out;           // (8, 2048, 4096) f32

    pack_kernel<<<256, NTHREADS>>>(cb);

    dim3 grid(NDG, NCHUNK, NB);                 // 8 x 32 x 8 = 2048 blocks
    scan_kernel<false><<<grid, NTHREADS>>>(idx, out);

    const float g64 = (float)pow(0.95, 64.0);   // host-side constant
    carry_kernel<<<(NB * DDIM / 4) / 256, 256>>>(g64);

    scan_kernel<true><<<grid, NTHREADS>>>(idx, out);
}

// round 4
// speedup vs baseline: 1.0042x; 1.0042x over previous
#include <cuda_runtime.h>
#include <cstdint>
#include <cmath>

// HDCProcessor: bit-domain exponential-decay scan, exact 3-phase form,
// with Blackwell packed-f32x2 math (FFMA2/FMUL2 via PTX fma/mul.rn.f32x2).
//   hdc[t,d] = 0.3*s(t,d) + 0.7*s(t,d)*s(t-1,d-1)*s(t-2,d-2)  (signs, rolls mod D)
//   acc_t = 0.95*acc_{t-1} + hdc_t ;  out[t] = acc_t * (1-g)/(1-g^{t+1})
// Phase 1: per-chunk partials (chunks 0..30 only; partial[31] is never used).
// Phase 2: carry scan over 32 chunks.
// Phase 3: re-run each chunk seeded with its exact carry, storing every step.

#define DDIM     4096
#define NB       8
#define NT       2048
#define NCHUNK   32
#define CLEN     64
#define NTHREADS 128
#define NDG      8                 // 4096 dims / (128 thr * 4 dims)
#define ROWW     17                // words per staged row: 1 halo + 16 slice
#define RWORDS   (256 * ROWW)      // 4352
#define ROWB     (ROWW * 4)        // staged row stride in bytes

__device__ uint32_t g_bitsx[NDG * RWORDS];   // per-dg pre-halo'd packed rows
__device__ float    g_inv[NT];               // (1-g)/(1-g^{t+1})
__device__ float    g_partial[NB * NCHUNK * DDIM];
__device__ float    g_carry[NB * NCHUNK * DDIM];

// ---- packed f32x2 helpers ----
__device__ __forceinline__ unsigned long long pk2(uint32_t lo, uint32_t hi) {
    unsigned long long r;
    asm("mov.b64 %0, {%1, %2};" : "=l"(r) : "r"(lo), "r"(hi));
    return r;
}
#define FMA2(d, a, b, c) \
    asm("fma.rn.f32x2 %0, %1, %2, %3;" : "=l"(d) : "l"(a), "l"(b), "l"(c))
#define MUL2(d, a, b) \
    asm("mul.rn.f32x2 %0, %1, %2;" : "=l"(d) : "l"(a), "l"(b))

#define G2   0x3F7333333F733333ull   // {0.95f, 0.95f}
#define W2K  0x3F3333333F333333ull   // {0.70f, 0.70f}

// ---- pack: sign bits of the bipolar codebook, expanded per d-group ----
__global__ void pack_kernel(const float* __restrict__ cb) {
    const int row  = blockIdx.x;
    const int lane = threadIdx.x & 31;
    const int w0   = threadIdx.x >> 5;
    for (int gw = w0; gw < 128; gw += 4) {
        float v = cb[row * DDIM + gw * 32 + lane];
        unsigned m = __ballot_sync(0xffffffffu, v < 0.0f);
        if (lane == 0) {
            g_bitsx[(gw >> 4) * RWORDS + row * ROWW + (gw & 15) + 1] = m;
            int gwn = (gw + 1) & 127;               // this word is the halo of
            if ((gwn & 15) == 0)                    // the next d-group (mod wrap)
                g_bitsx[(gwn >> 4) * RWORDS + row * ROWW] = m;
        }
    }
    int gid = blockIdx.x * NTHREADS + threadIdx.x;
    if (gid < NT)
        g_inv[gid] = (float)(0.05 / (1.0 - pow(0.95, (double)(gid + 1))));
}

// ---- phase 2: carry scan over chunks (carry[c] = sum_{e<c} g^(64*(c-e)) P[e]) ----
__global__ void carry_kernel(float g64) {
    const int gid = blockIdx.x * blockDim.x + threadIdx.x;  // 0 .. NB*DDIM/4-1
    const int b   = gid >> 10;                              // DDIM/4 = 1024
    const int d4  = gid & 1023;
    const float4* pp = (const float4*)g_partial + (size_t)b * NCHUNK * (DDIM / 4) + d4;
    float4*       cp = (float4*)g_carry        + (size_t)b * NCHUNK * (DDIM / 4) + d4;
    float4 a = make_float4(0.f, 0.f, 0.f, 0.f);
    cp[0] = a;
#pragma unroll
    for (int c = 0; c < NCHUNK - 1; c++) {
        float4 p = pp[c * (DDIM / 4)];
        a.x = fmaf(g64, a.x, p.x);
        a.y = fmaf(g64, a.y, p.y);
        a.z = fmaf(g64, a.z, p.z);
        a.w = fmaf(g64, a.w, p.w);
        cp[(c + 1) * (DDIM / 4)] = a;
    }
}

// ---- phases 1 & 3 ----
template <bool FINAL>
__global__ void __launch_bounds__(NTHREADS)
scan_kernel(const int* __restrict__ idx, float* __restrict__ out)
{
    const int dg    = blockIdx.x;
    const int chunk = blockIdx.y;
    const int b     = blockIdx.z;
    const int t0    = chunk * CLEN;
    const int tid   = threadIdx.x;

    __shared__ uint32_t s_bits[RWORDS + 4];
    __shared__ int      s_idx[CLEN + 2];                 // row byte offsets
    __shared__ unsigned long long s_inv2[CLEN];          // packed {inv, inv}

    // stage packed slice (contiguous uint4 copy, L2-resident source)
    {
        const uint4* src = (const uint4*)(g_bitsx + dg * RWORDS);
        uint4*       dst = (uint4*)s_bits;
        for (int k = tid; k < RWORDS / 4; k += NTHREADS) dst[k] = src[k];
    }
    if (tid < CLEN + 2) {
        int t = t0 - 2 + tid;
        s_idx[tid] = (t >= 0 ? idx[b * NT + t] : 0) * ROWB;
    }
    if (FINAL && tid < CLEN) {
        float v = g_inv[t0 + tid];
        s_inv2[tid] = pk2(__float_as_uint(v), __float_as_uint(v));
    }
    __syncthreads();

    // bit field: global dim (dg*512 + m) lives at staged-row bit (32 + m);
    // this thread needs dims d-2 .. d+3 => bits starting at p = 30 + 4*tid.
    const int p   = 30 + 4 * tid;
    const int q   = p >> 5;
    const int rsh = p & 31;
    const char* bbase = (const char*)(s_bits + q);

    uint32_t h1s = 0, h2s = 0;   // histories pre-shifted: f_{t-1}<<1, f_{t-2}<<2
    if (chunk) {
        const uint32_t* w1 = (const uint32_t*)(bbase + s_idx[1]);
        const uint32_t* w2 = (const uint32_t*)(bbase + s_idx[0]);
        h1s = __funnelshift_r(w1[0], w1[1], rsh) << 1;
        h2s = __funnelshift_r(w2[0], w2[1], rsh) << 2;
    }

    unsigned long long a01, a23;          // packed fp32 accumulators
    float* op = nullptr;
    if (FINAL) {
        const float4 cv = *(const float4*)(g_carry +
            ((size_t)(b * NCHUNK + chunk) * DDIM) + dg * 512 + 4 * tid);
        a01 = pk2(__float_as_uint(cv.x), __float_as_uint(cv.y));
        a23 = pk2(__float_as_uint(cv.z), __float_as_uint(cv.w));
        op = out + ((size_t)b * NT + t0) * DDIM + dg * 512 + 4 * tid;
    } else {
        a01 = 0ull; a23 = 0ull;
    }

    // one step: u_j = +-0.3 (cur sign), v_j = +-1 (trigram sign),
    // c = W*v + u (FFMA2), acc = 0.95*acc + c (FFMA2), out = acc*inv (FMUL2)
#define STEP(s, WP)                                                           \
    {                                                                         \
        const uint32_t* wp = (const uint32_t*)(bbase + s_idx[(s) + 2]);       \
        const uint32_t f = __funnelshift_r(wp[0], wp[1], rsh);                \
        const uint32_t Y = f ^ h1s ^ h2s;                                     \
        const uint32_t u0 = ((f << 29) & 0x80000000u) | 0x3E99999Au;          \
        const uint32_t u1 = ((f << 28) & 0x80000000u) | 0x3E99999Au;          \
        const uint32_t u2 = ((f << 27) & 0x80000000u) | 0x3E99999Au;          \
        const uint32_t u3 = ((f << 26) & 0x80000000u) | 0x3E99999Au;          \
        const uint32_t v0 = ((Y << 29) & 0x80000000u) | 0x3F800000u;          \
        const uint32_t v1 = ((Y << 28) & 0x80000000u) | 0x3F800000u;          \
        const uint32_t v2 = ((Y << 27) & 0x80000000u) | 0x3F800000u;          \
        const uint32_t v3 = ((Y << 26) & 0x80000000u) | 0x3F800000u;          \
        unsigned long long c01, c23;                                          \
        FMA2(c01, pk2(v0, v1), (WP), pk2(u0, u1));                            \
        FMA2(c23, pk2(v2, v3), (WP), pk2(u2, u3));                            \
        FMA2(a01, a01, G2, c01);                                              \
        FMA2(a23, a23, G2, c23);                                              \
        if (FINAL) {                                                          \
            const unsigned long long iv = s_inv2[(s)];                        \
            unsigned long long o01, o23;                                      \
            MUL2(o01, a01, iv);                                               \
            MUL2(o23, a23, iv);                                               \
            asm volatile("st.global.v2.b64 [%0], {%1, %2};"                   \
                         :: "l"(op), "l"(o01), "l"(o23) : "memory");          \
            op += DDIM;                                                       \
        }                                                                     \
        h2s = h1s << 1;                                                       \
        h1s = f << 1;                                                         \
    }

    if (chunk == 0) {
        // t = 0,1: reference zeroes the shifted-history rows -> trigram = 0
        STEP(0, 0ull)
        STEP(1, 0ull)
#pragma unroll 8
        for (int s = 2; s < CLEN; s++) STEP(s, W2K)
    } else {
#pragma unroll 8
        for (int s = 0; s < CLEN; s++) STEP(s, W2K)
    }
#undef STEP

    if (!FINAL) {
        float* pp = g_partial + ((size_t)(b * NCHUNK + chunk) * DDIM)
                    + dg * 512 + 4 * tid;
        asm volatile("st.global.v2.b64 [%0], {%1, %2};"
                     :: "l"(pp), "l"(a01), "l"(a23) : "memory");
    }
}

extern "C" void kernel_launch(void* const* d_in, const int* in_sizes, int n_in,
                              void* d_out, int out_size)
{
    const float* cb  = (const float*)d_in[0];   // (256, 4096) f32 bipolar
    const int*   idx = (const int*)d_in[1];     // (8, 2048) i32
    float*       out = (float*)d_out;           // (8, 2048, 4096) f32

    pack_kernel<<<256, NTHREADS>>>(cb);

    dim3 grid1(NDG, NCHUNK - 1, NB);            // partial[31] never needed
    scan_kernel<false><<<grid1, NTHREADS>>>(idx, out);

    const float g64 = (float)pow(0.95, 64.0);
    carry_kernel<<<(NB * DDIM / 4) / 256, 256>>>(g64);

    dim3 grid3(NDG, NCHUNK, NB);                // 8 x 32 x 8 = 2048 blocks
    scan_kernel<true><<<grid3, NTHREADS>>>(idx, out);
}

// round 6
// speedup vs baseline: 1.1136x; 1.1089x over previous
#include <cuda_runtime.h>
#include <cstdint>
#include <cmath>

// HDCProcessor: bit-domain exponential-decay scan, exact 3-phase form.
// R6: fixes R5's wsum8 Horner byte order (decay weights were time-reversed).
//   hdc[t,d] = 0.3*s(t,d) + 0.7*s(t,d)*s(t-1,d-1)*s(t-2,d-2)  (signs, rolls mod D)
//   acc_t = 0.95*acc_{t-1} + hdc_t ;  out[t] = acc_t * (1-g)/(1-g^{t+1})
// P1': partial[c][d] = C - 0.6*A_sigma - 1.4*A_tau, A = sum_k g^(63-k)*bit_k
//      via bit-transpose to time-major streams + 8 byte-LUT lookups +
//      Horner(g^8), low byte first so bit k gets weight g^(63-k).
// P2 : carry scan over 32 chunks. P3: exact seeded re-run with stores.

#define DDIM     4096
#define NB       8
#define NT       2048
#define NCHUNK   32
#define CLEN     64
#define NTHREADS 128
#define NDG      8                 // 4096 dims / (128 thr * 4 dims)
#define ROWW     17                // words per staged row: 1 halo + 16 slice
#define RWORDS   (256 * ROWW)      // 4352
#define ROWB     (ROWW * 4)        // staged row stride in bytes

__device__ uint32_t g_bitsx[NDG * RWORDS];   // per-dg pre-halo'd packed rows
__device__ float    g_inv[NT];               // (1-g)/(1-g^{t+1})
__device__ float    g_partial[NB * NCHUNK * DDIM];
__device__ float    g_carry[NB * NCHUNK * DDIM];

// ---- packed f32x2 helpers (P3) ----
__device__ __forceinline__ unsigned long long pk2(uint32_t lo, uint32_t hi) {
    unsigned long long r;
    asm("mov.b64 %0, {%1, %2};" : "=l"(r) : "r"(lo), "r"(hi));
    return r;
}
#define FMA2(d, a, b, c) \
    asm("fma.rn.f32x2 %0, %1, %2, %3;" : "=l"(d) : "l"(a), "l"(b), "l"(c))
#define MUL2(d, a, b) \
    asm("mul.rn.f32x2 %0, %1, %2;" : "=l"(d) : "l"(a), "l"(b))
#define G2   0x3F7333333F733333ull   // {0.95f, 0.95f}
#define W2K  0x3F3333333F333333ull   // {0.70f, 0.70f}

// ---- pack: sign bits of the bipolar codebook, expanded per d-group ----
__global__ void pack_kernel(const float* __restrict__ cb) {
    const int row  = blockIdx.x;
    const int lane = threadIdx.x & 31;
    const int w0   = threadIdx.x >> 5;
    for (int gw = w0; gw < 128; gw += 4) {
        float v = cb[row * DDIM + gw * 32 + lane];
        unsigned m = __ballot_sync(0xffffffffu, v < 0.0f);
        if (lane == 0) {
            g_bitsx[(gw >> 4) * RWORDS + row * ROWW + (gw & 15) + 1] = m;
            int gwn = (gw + 1) & 127;               // this word is the halo of
            if ((gwn & 15) == 0)                    // the next d-group (mod wrap)
                g_bitsx[(gwn >> 4) * RWORDS + row * ROWW] = m;
        }
    }
    int gid = blockIdx.x * NTHREADS + threadIdx.x;
    if (gid < NT)
        g_inv[gid] = (float)(0.05 / (1.0 - pow(0.95, (double)(gid + 1))));
}

// ---- P1': per-chunk partials via bit-transpose + byte-LUT sums ----
__device__ __forceinline__ uint32_t bt_stage(uint32_t x, int lane, int i, uint32_t m) {
    uint32_t y = __shfl_xor_sync(0xffffffffu, x, i);
    return (lane & i) ? ((x & ~m) | ((y >> i) & m))
                      : ((x & m) | ((y & m) << i));
}

// A = sum_{k=0..63} g^(63-k) * bit_k : low byte first (gets g^56 overall),
// hi>>24 last (multiplier 1); within-byte LUT weight g^(7-i) (bit 7 newest).
__device__ __forceinline__ float wsum8(uint32_t lo, uint32_t hi,
                                       const float* lut, float g8) {
    float a = lut[ lo        & 255];
    a = fmaf(a, g8, lut[(lo >>  8) & 255]);
    a = fmaf(a, g8, lut[(lo >> 16) & 255]);
    a = fmaf(a, g8, lut[ lo >> 24       ]);
    a = fmaf(a, g8, lut[ hi        & 255]);
    a = fmaf(a, g8, lut[(hi >>  8) & 255]);
    a = fmaf(a, g8, lut[(hi >> 16) & 255]);
    a = fmaf(a, g8, lut[ hi >> 24       ]);
    return a;
}

__global__ void __launch_bounds__(NTHREADS)
partial_kernel(const int* __restrict__ idx, float4 cs)
{
    // cs = {C, g^8, g^63, g^62}
    const int dg    = blockIdx.x;
    const int chunk = blockIdx.y;      // 0..30
    const int b     = blockIdx.z;
    const int t0    = chunk * CLEN;
    const int tid   = threadIdx.x;
    const int lane  = tid & 31;
    const int wid   = tid >> 5;

    __shared__ uint32_t s_rows[66 * ROWW + 1];  // row k = step k-2; +1 pad
    __shared__ uint32_t s_sig[2][544];          // [half][dim] time-major streams
    __shared__ float    s_lut[256];
    __shared__ int      s_row[66];

    if (tid < 66) {
        int t = t0 - 2 + tid;
        s_row[tid] = (t >= 0) ? idx[b * NT + t] : 0;
    }
    // byte LUT: lut[v] = sum_{i: bit i of v} g^(7-i)
    {
        const float w0 = 0.69833729609375f, w1 = 0.735091890625f,
                    w2 = 0.7737809375f,     w3 = 0.81450625f,
                    w4 = 0.857375f,         w5 = 0.9025f,
                    w6 = 0.95f,             w7 = 1.0f;
        for (int k = tid; k < 256; k += NTHREADS) {
            float v = 0.f;
            if (k & 1)   v += w0;
            if (k & 2)   v += w1;
            if (k & 4)   v += w2;
            if (k & 8)   v += w3;
            if (k & 16)  v += w4;
            if (k & 32)  v += w5;
            if (k & 64)  v += w6;
            if (k & 128) v += w7;
            s_lut[k] = v;
        }
    }
    __syncthreads();

    // stage the 66 needed rows (17 words each) from the pre-halo'd codebook
    for (int k = tid; k < 66 * ROWW; k += NTHREADS) {
        int r = k / ROWW, w = k - r * ROWW;
        s_rows[k] = g_bitsx[dg * RWORDS + s_row[r] * ROWW + w];
    }
    if (tid == 0) s_rows[66 * ROWW] = 0;
    __syncthreads();

    // warp bit-transpose: 17 word-cols x 2 step-halves -> time-major streams
    for (int task = wid; task < 34; task += 4) {
        const int col = task >> 1, half = task & 1;
        uint32_t x = s_rows[(half * 32 + lane + 2) * ROWW + col];
        x = bt_stage(x, lane, 16, 0x0000FFFFu);
        x = bt_stage(x, lane,  8, 0x00FF00FFu);
        x = bt_stage(x, lane,  4, 0x0F0F0F0Fu);
        x = bt_stage(x, lane,  2, 0x33333333u);
        x = bt_stage(x, lane,  1, 0x55555555u);
        s_sig[half][col * 32 + lane] = x;   // bit r = sign at step half*32+r
    }
    __syncthreads();

    // per-thread: 4 dims, n = 32 + 4*tid + j; needs streams n-2..n+3
    const int n0 = 32 + 4 * tid;
    uint32_t slo[6], shi[6];
#pragma unroll
    for (int j = 0; j < 6; j++) {
        slo[j] = s_sig[0][n0 - 2 + j];
        shi[j] = s_sig[1][n0 - 2 + j];
    }
    // history fields from rows t0-2 (staged row 0) and t0-1 (row 1)
    const int p   = 30 + 4 * tid;
    const int q   = p >> 5;
    const int rsh = p & 31;
    uint32_t fm2 = 0, fm1 = 0;
    if (chunk) {
        fm2 = __funnelshift_r(s_rows[q], s_rows[q + 1], rsh);
        fm1 = __funnelshift_r(s_rows[ROWW + q], s_rows[ROWW + q + 1], rsh);
    }

    float pv[4];
#pragma unroll
    for (int j = 0; j < 4; j++) {
        const uint32_t blo = slo[2 + j], bhi = shi[2 + j];
        const uint32_t e1  = (fm1 >> (1 + j)) & 1;
        const uint32_t l1  = (slo[1 + j] << 1) | e1;
        const uint32_t h1  = __funnelshift_l(slo[1 + j], shi[1 + j], 1);
        const uint32_t e2a = (fm2 >> j) & 1;
        const uint32_t e2b = (fm1 >> j) & 1;
        const uint32_t l2  = (slo[j] << 2) | (e2b << 1) | e2a;
        const uint32_t h2  = __funnelshift_l(slo[j], shi[j], 2);
        const uint32_t tlo = blo ^ l1 ^ l2;
        const uint32_t thi = bhi ^ h1 ^ h2;

        const float As = wsum8(blo, bhi, s_lut, cs.y);
        const float At = wsum8(tlo, thi, s_lut, cs.y);
        float v = fmaf(-0.6f, As, cs.x) - 1.4f * At;
        if (chunk == 0) {
            // steps 0,1 have zero trigram in the reference: remove spurious tau
            float s0 = 1.f - 2.f * (float)(tlo & 1);
            float s1 = 1.f - 2.f * (float)((tlo >> 1) & 1);
            v -= 0.7f * (s0 * cs.z + s1 * cs.w);
        }
        pv[j] = v;
    }
    float* pp = g_partial + ((size_t)(b * NCHUNK + chunk) * DDIM)
                + dg * 512 + 4 * tid;
    *(float4*)pp = make_float4(pv[0], pv[1], pv[2], pv[3]);
}

// ---- phase 2: carry scan over chunks ----
__global__ void carry_kernel(float g64) {
    const int gid = blockIdx.x * blockDim.x + threadIdx.x;  // 0 .. NB*DDIM/4-1
    const int b   = gid >> 10;                              // DDIM/4 = 1024
    const int d4  = gid & 1023;
    const float4* pp = (const float4*)g_partial + (size_t)b * NCHUNK * (DDIM / 4) + d4;
    float4*       cp = (float4*)g_carry        + (size_t)b * NCHUNK * (DDIM / 4) + d4;
    float4 a = make_float4(0.f, 0.f, 0.f, 0.f);
    cp[0] = a;
#pragma unroll
    for (int c = 0; c < NCHUNK - 1; c++) {
        float4 p = pp[c * (DDIM / 4)];
        a.x = fmaf(g64, a.x, p.x);
        a.y = fmaf(g64, a.y, p.y);
        a.z = fmaf(g64, a.z, p.z);
        a.w = fmaf(g64, a.w, p.w);
        cp[(c + 1) * (DDIM / 4)] = a;
    }
}

// ---- phase 3: seeded exact scan with stores (proven in R3/R4) ----
__global__ void __launch_bounds__(NTHREADS)
scan_kernel(const int* __restrict__ idx, float* __restrict__ out)
{
    const int dg    = blockIdx.x;
    const int chunk = blockIdx.y;
    const int b     = blockIdx.z;
    const int t0    = chunk * CLEN;
    const int tid   = threadIdx.x;

    __shared__ uint32_t s_bits[RWORDS + 4];
    __shared__ int      s_idx[CLEN + 2];                 // row byte offsets
    __shared__ unsigned long long s_inv2[CLEN];          // packed {inv, inv}

    {
        const uint4* src = (const uint4*)(g_bitsx + dg * RWORDS);
        uint4*       dst = (uint4*)s_bits;
        for (int k = tid; k < RWORDS / 4; k += NTHREADS) dst[k] = src[k];
    }
    if (tid < CLEN + 2) {
        int t = t0 - 2 + tid;
        s_idx[tid] = (t >= 0 ? idx[b * NT + t] : 0) * ROWB;
    }
    if (tid < CLEN) {
        float v = g_inv[t0 + tid];
        s_inv2[tid] = pk2(__float_as_uint(v), __float_as_uint(v));
    }
    __syncthreads();

    const int p   = 30 + 4 * tid;
    const int q   = p >> 5;
    const int rsh = p & 31;
    const char* bbase = (const char*)(s_bits + q);

    uint32_t h1s = 0, h2s = 0;
    if (chunk) {
        const uint32_t* w1 = (const uint32_t*)(bbase + s_idx[1]);
        const uint32_t* w2 = (const uint32_t*)(bbase + s_idx[0]);
        h1s = __funnelshift_r(w1[0], w1[1], rsh) << 1;
        h2s = __funnelshift_r(w2[0], w2[1], rsh) << 2;
    }

    unsigned long long a01, a23;
    const float4 cv = *(const float4*)(g_carry +
        ((size_t)(b * NCHUNK + chunk) * DDIM) + dg * 512 + 4 * tid);
    a01 = pk2(__float_as_uint(cv.x), __float_as_uint(cv.y));
    a23 = pk2(__float_as_uint(cv.z), __float_as_uint(cv.w));
    float* op = out + ((size_t)b * NT + t0) * DDIM + dg * 512 + 4 * tid;

#define STEP(s, WP)                                                           \
    {                                                                         \
        const uint32_t* wp = (const uint32_t*)(bbase + s_idx[(s) + 2]);       \
        const uint32_t f = __funnelshift_r(wp[0], wp[1], rsh);                \
        const uint32_t Y = f ^ h1s ^ h2s;                                     \
        const uint32_t u0 = ((f << 29) & 0x80000000u) | 0x3E99999Au;          \
        const uint32_t u1 = ((f << 28) & 0x80000000u) | 0x3E99999Au;          \
        const uint32_t u2 = ((f << 27) & 0x80000000u) | 0x3E99999Au;          \
        const uint32_t u3 = ((f << 26) & 0x80000000u) | 0x3E99999Au;          \
        const uint32_t v0 = ((Y << 29) & 0x80000000u) | 0x3F800000u;          \
        const uint32_t v1 = ((Y << 28) & 0x80000000u) | 0x3F800000u;          \
        const uint32_t v2 = ((Y << 27) & 0x80000000u) | 0x3F800000u;          \
        const uint32_t v3 = ((Y << 26) & 0x80000000u) | 0x3F800000u;          \
        unsigned long long c01, c23;                                          \
        FMA2(c01, pk2(v0, v1), (WP), pk2(u0, u1));                            \
        FMA2(c23, pk2(v2, v3), (WP), pk2(u2, u3));                            \
        FMA2(a01, a01, G2, c01);                                              \
        FMA2(a23, a23, G2, c23);                                              \
        {                                                                     \
            const unsigned long long iv = s_inv2[(s)];                        \
            unsigned long long o01, o23;                                      \
            MUL2(o01, a01, iv);                                               \
            MUL2(o23, a23, iv);                                               \
            asm volatile("st.global.v2.b64 [%0], {%1, %2};"                   \
                         :: "l"(op), "l"(o01), "l"(o23) : "memory");          \
            op += DDIM;                                                       \
        }                                                                     \
        h2s = h1s << 1;                                                       \
        h1s = f << 1;                                                         \
    }

    if (chunk == 0) {
        STEP(0, 0ull)
        STEP(1, 0ull)
#pragma unroll 8
        for (int s = 2; s < CLEN; s++) STEP(s, W2K)
    } else {
#pragma unroll 8
        for (int s = 0; s < CLEN; s++) STEP(s, W2K)
    }
#undef STEP
}

extern "C" void kernel_launch(void* const* d_in, const int* in_sizes, int n_in,
                              void* d_out, int out_size)
{
    const float* cb  = (const float*)d_in[0];   // (256, 4096) f32 bipolar
    const int*   idx = (const int*)d_in[1];     // (8, 2048) i32
    float*       out = (float*)d_out;           // (8, 2048, 4096) f32

    pack_kernel<<<256, NTHREADS>>>(cb);

    const double g = 0.95;
    float4 cs;
    cs.x = (float)((1.0 - pow(g, 64.0)) / 0.05);   // C = sum_{j<64} g^j
    cs.y = (float)pow(g, 8.0);
    cs.z = (float)pow(g, 63.0);
    cs.w = (float)pow(g, 62.0);

    dim3 grid1(NDG, NCHUNK - 1, NB);            // chunks 0..30
    partial_kernel<<<grid1, NTHREADS>>>(idx, cs);

    carry_kernel<<<(NB * DDIM / 4) / 256, 256>>>((float)pow(g, 64.0));

    dim3 grid3(NDG, NCHUNK, NB);
    scan_kernel<<<grid3, NTHREADS>>>(idx, out);
}

// round 7
// speedup vs baseline: 1.2229x; 1.0982x over previous
#include <cuda_runtime.h>
#include <cstdint>
#include <cmath>

// HDCProcessor: bit-domain exponential-decay scan, single fused kernel.
//   hdc[t,d] = 0.3*s(t,d) + 0.7*s(t,d)*s(t-1,d-1)*s(t-2,d-2)  (signs, rolls mod D)
//   acc_t = 0.95*acc_{t-1} + hdc_t ;  out[t] = acc_t * (1-g)/(1-g^{t+1})
// T split into 8 chunks of 256; chunks 1..7 run a 192-step store-free warmup
// (truncation ~1.3e-5 rel: R2 measured 2.97e-5 @WUP=176, x g^16; gate 1e-3).
// Codebook is bipolar: sign bits pre-packed per 512-dim slice with a 32-bit
// halo (pack_kernel), staged to smem; the scan loop has zero global loads.

#define DDIM     4096
#define NB       8
#define NT       2048
#define NCHUNK   8
#define CLEN     256
#define WUP      192
#define NTHREADS 128
#define NDG      8                 // 4096 dims / (128 thr * 4 dims)
#define ROWW     17                // words per staged row: 1 halo + 16 slice
#define RWORDS   (256 * ROWW)      // 4352
#define ROWB     (ROWW * 4)        // staged row stride in bytes
#define SIDXN    (CLEN + WUP + 2)  // 450

__device__ uint32_t g_bitsx[NDG * RWORDS];   // per-dg pre-halo'd packed rows
__device__ float    g_inv[NT];               // (1-g)/(1-g^{t+1})

// ---- packed f32x2 helpers ----
__device__ __forceinline__ unsigned long long pk2(uint32_t lo, uint32_t hi) {
    unsigned long long r;
    asm("mov.b64 %0, {%1, %2};" : "=l"(r) : "r"(lo), "r"(hi));
    return r;
}
#define FMA2(d, a, b, c) \
    asm("fma.rn.f32x2 %0, %1, %2, %3;" : "=l"(d) : "l"(a), "l"(b), "l"(c))
#define MUL2(d, a, b) \
    asm("mul.rn.f32x2 %0, %1, %2;" : "=l"(d) : "l"(a), "l"(b))
#define G2   0x3F7333333F733333ull   // {0.95f, 0.95f}
#define W2K  0x3F3333333F333333ull   // {0.70f, 0.70f}

// ---- pack: sign bits of the bipolar codebook, expanded per d-group ----
__global__ void pack_kernel(const float* __restrict__ cb) {
    const int row  = blockIdx.x;
    const int lane = threadIdx.x & 31;
    const int w0   = threadIdx.x >> 5;
    for (int gw = w0; gw < 128; gw += 4) {
        float v = cb[row * DDIM + gw * 32 + lane];
        unsigned m = __ballot_sync(0xffffffffu, v < 0.0f);
        if (lane == 0) {
            g_bitsx[(gw >> 4) * RWORDS + row * ROWW + (gw & 15) + 1] = m;
            int gwn = (gw + 1) & 127;               // this word is the halo of
            if ((gwn & 15) == 0)                    // the next d-group (mod wrap)
                g_bitsx[(gwn >> 4) * RWORDS + row * ROWW] = m;
        }
    }
    int gid = blockIdx.x * NTHREADS + threadIdx.x;
    if (gid < NT)
        g_inv[gid] = (float)(0.05 / (1.0 - pow(0.95, (double)(gid + 1))));
}

// ---- fused scan: warmup (no stores) + store phase ----
__global__ void __launch_bounds__(NTHREADS)
scan_kernel(const int* __restrict__ idx, float* __restrict__ out)
{
    const int dg    = blockIdx.x;
    const int chunk = blockIdx.y;
    const int b     = blockIdx.z;
    const int t0    = chunk * CLEN;
    const int tid   = threadIdx.x;

    __shared__ uint32_t s_bits[RWORDS + 4];
    __shared__ int      s_idx[SIDXN];                    // row byte offsets
    __shared__ unsigned long long s_inv2[CLEN];          // packed {inv, inv}

    // stage packed codebook slice (contiguous uint4 copy, L2-resident source)
    {
        const uint4* src = (const uint4*)(g_bitsx + dg * RWORDS);
        uint4*       dst = (uint4*)s_bits;
        for (int k = tid; k < RWORDS / 4; k += NTHREADS) dst[k] = src[k];
    }
    const int nwarm = chunk ? WUP : 0;
    const int ts    = t0 - nwarm;        // first scanned timestep
    for (int k = tid; k < SIDXN; k += NTHREADS) {
        int t = ts - 2 + k;              // tail entries past nsteps are unused
        s_idx[k] = ((t >= 0 && t < NT) ? idx[b * NT + t] : 0) * ROWB;
    }
    for (int k = tid; k < CLEN; k += NTHREADS) {
        float v = g_inv[t0 + k];
        s_inv2[k] = pk2(__float_as_uint(v), __float_as_uint(v));
    }
    __syncthreads();

    // bit field: global dim (dg*512 + m) lives at staged-row bit (32 + m);
    // this thread needs dims d-2 .. d+3 => bits starting at p = 30 + 4*tid.
    const int p   = 30 + 4 * tid;
    const int q   = p >> 5;
    const int rsh = p & 31;
    const char* bbase = (const char*)(s_bits + q);

    uint32_t h1s = 0, h2s = 0;   // histories pre-shifted: f_{t-1}<<1, f_{t-2}<<2
    if (chunk) {                 // ts >= 64, rows ts-1/ts-2 always valid
        const uint32_t* w1 = (const uint32_t*)(bbase + s_idx[1]);
        const uint32_t* w2 = (const uint32_t*)(bbase + s_idx[0]);
        h1s = __funnelshift_r(w1[0], w1[1], rsh) << 1;
        h2s = __funnelshift_r(w2[0], w2[1], rsh) << 2;
    }

    unsigned long long a01 = 0ull, a23 = 0ull;   // packed fp32 accumulators
    float* op = out + ((size_t)b * NT + t0) * DDIM + dg * 512 + 4 * tid;

    // core update: u = +-0.3 (cur sign), v = +-1 (trigram sign),
    // c = W*v + u (FFMA2), acc = 0.95*acc + c (FFMA2)
#define CORE(sp, WP)                                                          \
        const uint32_t* wp = (const uint32_t*)(bbase + s_idx[(sp)]);          \
        const uint32_t f = __funnelshift_r(wp[0], wp[1], rsh);                \
        const uint32_t Y = f ^ h1s ^ h2s;                                     \
        const uint32_t u0 = ((f << 29) & 0x80000000u) | 0x3E99999Au;          \
        const uint32_t u1 = ((f << 28) & 0x80000000u) | 0x3E99999Au;          \
        const uint32_t u2 = ((f << 27) & 0x80000000u) | 0x3E99999Au;          \
        const uint32_t u3 = ((f << 26) & 0x80000000u) | 0x3E99999Au;          \
        const uint32_t v0 = ((Y << 29) & 0x80000000u) | 0x3F800000u;          \
        const uint32_t v1 = ((Y << 28) & 0x80000000u) | 0x3F800000u;          \
        const uint32_t v2 = ((Y << 27) & 0x80000000u) | 0x3F800000u;          \
        const uint32_t v3 = ((Y << 26) & 0x80000000u) | 0x3F800000u;          \
        unsigned long long c01, c23;                                          \
        FMA2(c01, pk2(v0, v1), (WP), pk2(u0, u1));                            \
        FMA2(c23, pk2(v2, v3), (WP), pk2(u2, u3));                            \
        FMA2(a01, a01, G2, c01);                                              \
        FMA2(a23, a23, G2, c23);                                              \
        h2s = h1s << 1;                                                       \
        h1s = f << 1;

#define STEPW(w)                                                              \
    {   CORE((w) + 2, W2K)   }

#define STEPS(sp, s, WP)                                                      \
    {   CORE((sp) + 2, WP)                                                    \
        const unsigned long long iv = s_inv2[(s)];                            \
        unsigned long long o01, o23;                                          \
        MUL2(o01, a01, iv);                                                   \
        MUL2(o23, a23, iv);                                                   \
        asm volatile("st.global.v2.b64 [%0], {%1, %2};"                       \
                     :: "l"(op), "l"(o01), "l"(o23) : "memory");              \
        op += DDIM;                                                           \
    }

    if (chunk == 0) {
        // t = 0,1: reference zeroes the shifted-history rows -> trigram = 0
        STEPS(0, 0, 0ull)
        STEPS(1, 1, 0ull)
#pragma unroll 8
        for (int s = 2; s < CLEN; s++) STEPS(s, s, W2K)
    } else {
#pragma unroll 8
        for (int w = 0; w < WUP; w++) STEPW(w)
#pragma unroll 8
        for (int s = 0; s < CLEN; s++) STEPS(WUP + s, s, W2K)
    }
#undef CORE
#undef STEPW
#undef STEPS
}

extern "C" void kernel_launch(void* const* d_in, const int* in_sizes, int n_in,
                              void* d_out, int out_size)
{
    const float* cb  = (const float*)d_in[0];   // (256, 4096) f32 bipolar
    const int*   idx = (const int*)d_in[1];     // (8, 2048) i32
    float*       out = (float*)d_out;           // (8, 2048, 4096) f32

    pack_kernel<<<256, NTHREADS>>>(cb);

    dim3 grid(NDG, NCHUNK, NB);                 // 8 x 8 x 8 = 512 blocks
    scan_kernel<<<grid, NTHREADS>>>(idx, out);
}

// round 8
// speedup vs baseline: 1.4116x; 1.1543x over previous
#include <cuda_runtime.h>
#include <cstdint>
#include <cmath>

// HDCProcessor: bit-domain exponential-decay scan, single fused kernel.
// R8: TMA 1D bulk-store epilogue (STS + cp.async.bulk, per-warp double buffer)
//     replaces per-step STG.128 (12-cyc LSU issue cost was the store binder);
//     WUP 192 -> 144 (rel_err ~1.1e-4, gate 1e-3).
//   hdc[t,d] = 0.3*s(t,d) + 0.7*s(t,d)*s(t-1,d-1)*s(t-2,d-2)  (signs, rolls mod D)
//   acc_t = 0.95*acc_{t-1} + hdc_t ;  out[t] = acc_t * (1-g)/(1-g^{t+1})

#define DDIM     4096
#define NB       8
#define NT       2048
#define NCHUNK   8
#define CLEN     256
#define WUP      144
#define NTHREADS 128
#define NDG      8                 // 4096 dims / (128 thr * 4 dims)
#define ROWW     17                // words per staged row: 1 halo + 16 slice
#define RWORDS   (256 * ROWW)      // 4352
#define ROWB     (ROWW * 4)
#define SIDXN    (CLEN + WUP + 2)  // 402
#define NBATCH   (CLEN / 8)        // 32 epilogue batches of 8 steps

// dynamic smem layout (bytes)
#define OFF_BITS  0
#define SZ_BITS   ((RWORDS + 4) * 4)                   // 17424
#define OFF_IDX   (OFF_BITS + SZ_BITS)
#define SZ_IDX    (SIDXN * 4)                          // 1608
#define OFF_INV   ((OFF_IDX + SZ_IDX + 15) & ~15)
#define SZ_INV    (CLEN * 8)                           // 2048
#define OFF_STAGE ((OFF_INV + SZ_INV + 15) & ~15)
#define SZ_STAGE  (4 * 2 * 8 * 512)                    // 4 warps x 2 buf x 8 steps x 512B
#define SMEM_DYN  (OFF_STAGE + SZ_STAGE)               // ~53.9 KB

__device__ uint32_t g_bitsx[NDG * RWORDS];   // per-dg pre-halo'd packed rows
__device__ float    g_inv[NT];               // (1-g)/(1-g^{t+1})

// ---- packed f32x2 helpers ----
__device__ __forceinline__ unsigned long long pk2(uint32_t lo, uint32_t hi) {
    unsigned long long r;
    asm("mov.b64 %0, {%1, %2};" : "=l"(r) : "r"(lo), "r"(hi));
    return r;
}
#define FMA2(d, a, b, c) \
    asm("fma.rn.f32x2 %0, %1, %2, %3;" : "=l"(d) : "l"(a), "l"(b), "l"(c))
#define MUL2(d, a, b) \
    asm("mul.rn.f32x2 %0, %1, %2;" : "=l"(d) : "l"(a), "l"(b))
#define G2   0x3F7333333F733333ull   // {0.95f, 0.95f}
#define W2K  0x3F3333333F333333ull   // {0.70f, 0.70f}

// ---- pack: sign bits of the bipolar codebook, expanded per d-group ----
__global__ void pack_kernel(const float* __restrict__ cb) {
    const int row  = blockIdx.x;
    const int lane = threadIdx.x & 31;
    const int wq   = (blockIdx.y << 2) + (threadIdx.x >> 5);  // word quarter 0..15
    for (int k = 0; k < 8; k++) {
        int gw = wq * 8 + k;
        float v = cb[row * DDIM + gw * 32 + lane];
        unsigned m = __ballot_sync(0xffffffffu, v < 0.0f);
        if (lane == 0) {
            g_bitsx[(gw >> 4) * RWORDS + row * ROWW + (gw & 15) + 1] = m;
            int gwn = (gw + 1) & 127;               // this word is the halo of
            if ((gwn & 15) == 0)                    // the next d-group (mod wrap)
                g_bitsx[(gwn >> 4) * RWORDS + row * ROWW] = m;
        }
    }
    if (blockIdx.y == 0) {
        int gid = blockIdx.x * NTHREADS + threadIdx.x;
        if (gid < NT)
            g_inv[gid] = (float)(0.05 / (1.0 - pow(0.95, (double)(gid + 1))));
    }
}

// ---- fused scan: store-free warmup + TMA-store epilogue ----
__global__ void __launch_bounds__(NTHREADS)
scan_kernel(const int* __restrict__ idx, float* __restrict__ out)
{
    extern __shared__ char smem[];
    uint32_t smem_base;
    asm("{ .reg .u64 t; cvta.to.shared.u64 t, %1; cvt.u32.u64 %0, t; }"
        : "=r"(smem_base) : "l"(smem));

    uint32_t* s_bits = (uint32_t*)(smem + OFF_BITS);
    int*      s_idx  = (int*)(smem + OFF_IDX);
    unsigned long long* s_inv2 = (unsigned long long*)(smem + OFF_INV);

    const int dg    = blockIdx.x;
    const int chunk = blockIdx.y;
    const int b     = blockIdx.z;
    const int t0    = chunk * CLEN;
    const int tid   = threadIdx.x;
    const int lane  = tid & 31;
    const int wid   = tid >> 5;

    // stage packed codebook slice (contiguous uint4 copy, L2-resident source)
    {
        const uint4* src = (const uint4*)(g_bitsx + dg * RWORDS);
        uint4*       dst = (uint4*)s_bits;
        for (int k = tid; k < RWORDS / 4; k += NTHREADS) dst[k] = src[k];
    }
    const int nwarm = chunk ? WUP : 0;
    const int ts    = t0 - nwarm;        // first scanned timestep
    for (int k = tid; k < SIDXN; k += NTHREADS) {
        int t = ts - 2 + k;              // tail entries past nsteps are unused
        s_idx[k] = ((t >= 0 && t < NT) ? idx[b * NT + t] : 0) * ROWB;
    }
    for (int k = tid; k < CLEN; k += NTHREADS) {
        float v = g_inv[t0 + k];
        s_inv2[k] = pk2(__float_as_uint(v), __float_as_uint(v));
    }
    __syncthreads();

    // bit field: global dim (dg*512 + m) lives at staged-row bit (32 + m);
    // this thread needs dims d-2 .. d+3 => bits starting at p = 30 + 4*tid.
    const int p   = 30 + 4 * tid;
    const int q   = p >> 5;
    const int rsh = p & 31;
    const char* bbase = (const char*)(s_bits + q);

    uint32_t h1s = 0, h2s = 0;   // histories pre-shifted: f_{t-1}<<1, f_{t-2}<<2
    if (chunk) {                 // ts >= 112, rows ts-1/ts-2 always valid
        const uint32_t* w1 = (const uint32_t*)(bbase + s_idx[1]);
        const uint32_t* w2 = (const uint32_t*)(bbase + s_idx[0]);
        h1s = __funnelshift_r(w1[0], w1[1], rsh) << 1;
        h2s = __funnelshift_r(w2[0], w2[1], rsh) << 2;
    }

    unsigned long long a01 = 0ull, a23 = 0ull;   // packed fp32 accumulators

#define CORE(sp, WP)                                                          \
        const uint32_t* wp = (const uint32_t*)(bbase + s_idx[(sp)]);          \
        const uint32_t f = __funnelshift_r(wp[0], wp[1], rsh);                \
        const uint32_t Y = f ^ h1s ^ h2s;                                     \
        const uint32_t u0 = ((f << 29) & 0x80000000u) | 0x3E99999Au;          \
        const uint32_t u1 = ((f << 28) & 0x80000000u) | 0x3E99999Au;          \
        const uint32_t u2 = ((f << 27) & 0x80000000u) | 0x3E99999Au;          \
        const uint32_t u3 = ((f << 26) & 0x80000000u) | 0x3E99999Au;          \
        const uint32_t v0 = ((Y << 29) & 0x80000000u) | 0x3F800000u;          \
        const uint32_t v1 = ((Y << 28) & 0x80000000u) | 0x3F800000u;          \
        const uint32_t v2 = ((Y << 27) & 0x80000000u) | 0x3F800000u;          \
        const uint32_t v3 = ((Y << 26) & 0x80000000u) | 0x3F800000u;          \
        unsigned long long c01, c23;                                          \
        FMA2(c01, pk2(v0, v1), (WP), pk2(u0, u1));                            \
        FMA2(c23, pk2(v2, v3), (WP), pk2(u2, u3));                            \
        FMA2(a01, a01, G2, c01);                                              \
        FMA2(a23, a23, G2, c23);                                              \
        h2s = h1s << 1;                                                       \
        h1s = f << 1;

    // ---- warmup (no stores) ----
    if (chunk) {
#pragma unroll 8
        for (int w = 0; w < WUP; w++) { CORE(w + 2, W2K) }
    }

    // ---- epilogue: 32 batches of 8 steps, STS -> per-warp TMA bulk store ----
    const uint32_t stg_warp = smem_base + OFF_STAGE + wid * 8192;
    float* gbase = out + ((size_t)b * NT + t0) * DDIM + dg * 512 + wid * 128;
    const unsigned long long wfirst = chunk ? W2K : 0ull;  // t=0,1: trigram zeroed

#pragma unroll 1
    for (int bt = 0; bt < NBATCH; bt++) {
        if (bt >= 2)   // buffer (bt & 1) free once group bt-2 has been read out
            asm volatile("cp.async.bulk.wait_group.read 1;" ::: "memory");
        const uint32_t stg_buf = stg_warp + (bt & 1) * 4096;
#pragma unroll
        for (int j = 0; j < 8; j++) {
            const int s = bt * 8 + j;
            unsigned long long WPsel =
                (bt == 0 && j < 2) ? wfirst : W2K;       // compile-time per j
            { CORE(nwarm + s + 2, WPsel)
              const unsigned long long iv = s_inv2[s];
              unsigned long long o01, o23;
              MUL2(o01, a01, iv);
              MUL2(o23, a23, iv);
              asm volatile("st.shared.v2.u64 [%0], {%1, %2};"
                           :: "r"(stg_buf + j * 512 + lane * 16),
                              "l"(o01), "l"(o23) : "memory");
            }
        }
        __syncwarp();
        asm volatile("fence.proxy.async.shared::cta;" ::: "memory");
        // lanes 0..7 each bulk-copy one 512B row (step bt*8+lane) to gmem
        {
            float* gdst = gbase + (size_t)lane * DDIM;   // valid for lane<8 only
            asm volatile(
                "{\n\t.reg .pred p;\n\t"
                "setp.lt.u32 p, %0, 8;\n\t"
                "@p cp.async.bulk.global.shared::cta.bulk_group [%1], [%2], 512;\n\t"
                "}"
                :: "r"(lane), "l"(gdst), "r"(stg_buf + lane * 512) : "memory");
            asm volatile("cp.async.bulk.commit_group;" ::: "memory");
        }
        gbase += 8 * DDIM;
    }
#undef CORE
    asm volatile("cp.async.bulk.wait_group 0;" ::: "memory");
}

extern "C" void kernel_launch(void* const* d_in, const int* in_sizes, int n_in,
                              void* d_out, int out_size)
{
    const float* cb  = (const float*)d_in[0];   // (256, 4096) f32 bipolar
    const int*   idx = (const int*)d_in[1];     // (8, 2048) i32
    float*       out = (float*)d_out;           // (8, 2048, 4096) f32

    static bool attr_done = false;
    if (!attr_done) {
        cudaFuncSetAttribute(scan_kernel,
                             cudaFuncAttributeMaxDynamicSharedMemorySize,
                             SMEM_DYN);
        attr_done = true;
    }

    dim3 pgrid(256, 4);
    pack_kernel<<<pgrid, NTHREADS>>>(cb);

    dim3 grid(NDG, NCHUNK, NB);                 // 8 x 8 x 8 = 512 blocks
    scan_kernel<<<grid, NTHREADS, SMEM_DYN>>>(idx, out);
}

// round 10
// speedup vs baseline: 1.6142x; 1.1435x over previous
#include <cuda_runtime.h>
#include <cstdint>
#include <cmath>

// HDCProcessor: bit-domain exponential-decay scan, single fused kernel.
// R10: fixes R9's LUT index (trigram bits are Y>>2-aligned, matching f).
//   c-value smem LUT (16 x float2) replaces the 16-op sign construction;
//   STG.128 epilogue; NCHUNK=16/CLEN=128 -> 1024 blocks (~28 warps/SM).
//   hdc[t,d] = 0.3*s(t,d) + 0.7*s(t,d)*s(t-1,d-1)*s(t-2,d-2)  (signs, rolls mod D)
//   acc_t = 0.95*acc_{t-1} + hdc_t ;  out[t] = acc_t * (1-g)/(1-g^{t+1})
// c takes only values {+-1.0, +-0.4}: LUT[f1 f0 y1 y0] = {c_j, c_j+1}.
// Chunks 0,1 are exact (start at t=0); chunks >=2 use a 144-step warmup
// (truncation ~1.1e-4 rel, measured in R8; gate 1e-3).

#define DDIM     4096
#define NB       8
#define NT       2048
#define NCHUNK   16
#define CLEN     128
#define WUP      144
#define NTHREADS 128
#define NDG      8                 // 4096 dims / (128 thr * 4 dims)
#define ROWW     17                // words per staged row: 1 halo + 16 slice
#define RWORDS   (256 * ROWW)      // 4352
#define ROWB     (ROWW * 4)
#define SIDXN    (CLEN + WUP + 2)  // 274

__device__ uint32_t g_bitsx[NDG * RWORDS];   // per-dg pre-halo'd packed rows
__device__ float    g_inv[NT];               // (1-g)/(1-g^{t+1})

// ---- packed f32x2 helpers ----
__device__ __forceinline__ unsigned long long pk2(uint32_t lo, uint32_t hi) {
    unsigned long long r;
    asm("mov.b64 %0, {%1, %2};" : "=l"(r) : "r"(lo), "r"(hi));
    return r;
}
#define FMA2(d, a, b, c) \
    asm("fma.rn.f32x2 %0, %1, %2, %3;" : "=l"(d) : "l"(a), "l"(b), "l"(c))
#define MUL2(d, a, b) \
    asm("mul.rn.f32x2 %0, %1, %2;" : "=l"(d) : "l"(a), "l"(b))
#define G2   0x3F7333333F733333ull   // {0.95f, 0.95f}

// ---- pack: sign bits of the bipolar codebook, expanded per d-group ----
__global__ void pack_kernel(const float* __restrict__ cb) {
    const int row  = blockIdx.x;
    const int lane = threadIdx.x & 31;
    const int wq   = (blockIdx.y << 2) + (threadIdx.x >> 5);  // word quarter 0..15
    for (int k = 0; k < 8; k++) {
        int gw = wq * 8 + k;
        float v = cb[row * DDIM + gw * 32 + lane];
        unsigned m = __ballot_sync(0xffffffffu, v < 0.0f);
        if (lane == 0) {
            g_bitsx[(gw >> 4) * RWORDS + row * ROWW + (gw & 15) + 1] = m;
            int gwn = (gw + 1) & 127;               // this word is the halo of
            if ((gwn & 15) == 0)                    // the next d-group (mod wrap)
                g_bitsx[(gwn >> 4) * RWORDS + row * ROWW] = m;
        }
    }
    if (blockIdx.y == 0) {
        int gid = blockIdx.x * NTHREADS + threadIdx.x;
        if (gid < NT)
            g_inv[gid] = (float)(0.05 / (1.0 - pow(0.95, (double)(gid + 1))));
    }
}

// ---- fused scan ----
__global__ void __launch_bounds__(NTHREADS)
scan_kernel(const int* __restrict__ idx, float* __restrict__ out)
{
    const int dg    = blockIdx.x;
    const int chunk = blockIdx.y;
    const int b     = blockIdx.z;
    const int t0    = chunk * CLEN;
    const int tid   = threadIdx.x;

    __shared__ uint32_t s_bits[RWORDS + 4];
    __shared__ int      s_idx[SIDXN];                    // row byte offsets
    __shared__ unsigned long long s_inv2[CLEN];          // packed {inv, inv}
    __shared__ unsigned long long s_lut[16];             // packed {c_j, c_j+1}

    // c LUT: index [f1 f0 y1 y0]; c = 0.3*(f?-1:+1) + 0.7*(y?-1:+1)
    if (tid < 16) {
        float c0 = ((tid & 4) ? -0.3f : 0.3f) + ((tid & 1) ? -0.7f : 0.7f);
        float c1 = ((tid & 8) ? -0.3f : 0.3f) + ((tid & 2) ? -0.7f : 0.7f);
        s_lut[tid] = pk2(__float_as_uint(c0), __float_as_uint(c1));
    }
    // stage packed codebook slice (contiguous uint4 copy, L2-resident source)
    {
        const uint4* src = (const uint4*)(g_bitsx + dg * RWORDS);
        uint4*       dst = (uint4*)s_bits;
        for (int k = tid; k < RWORDS / 4; k += NTHREADS) dst[k] = src[k];
    }
    const int nwarm = (t0 - WUP > 0) ? WUP : t0;   // chunk0:0, chunk1:128, else 144
    const int ts    = t0 - nwarm;                  // first scanned timestep
    for (int k = tid; k < SIDXN; k += NTHREADS) {
        int t = ts - 2 + k;              // tail entries past nsteps are unused
        s_idx[k] = ((t >= 0 && t < NT) ? idx[b * NT + t] : 0) * ROWB;
    }
    for (int k = tid; k < CLEN; k += NTHREADS) {
        float v = g_inv[t0 + k];
        s_inv2[k] = pk2(__float_as_uint(v), __float_as_uint(v));
    }
    __syncthreads();

    // bit field: global dim (dg*512 + m) lives at staged-row bit (32 + m);
    // this thread needs dims d-2 .. d+3 => bits starting at p = 30 + 4*tid.
    // Both f (cur) and Y (trigram) carry dim j's sign at bit (2+j).
    const int p   = 30 + 4 * tid;
    const int q   = p >> 5;
    const int rsh = p & 31;
    const char* bbase = (const char*)(s_bits + q);
    const char* lutb  = (const char*)s_lut;

    uint32_t h1s = 0, h2s = 0;   // histories pre-shifted: f_{t-1}<<1, f_{t-2}<<2
    if (ts >= 2) {               // real history (chunk>=2)
        const uint32_t* w1 = (const uint32_t*)(bbase + s_idx[1]);
        const uint32_t* w2 = (const uint32_t*)(bbase + s_idx[0]);
        h1s = __funnelshift_r(w1[0], w1[1], rsh) << 1;
        h2s = __funnelshift_r(w2[0], w2[1], rsh) << 2;
    }

    unsigned long long a01 = 0ull, a23 = 0ull;   // packed fp32 accumulators
    float* op = out + ((size_t)b * NT + t0) * DDIM + dg * 512 + 4 * tid;

    // LUT core: index bits [f(dim j+1), f(dim j), y(dim j+1), y(dim j)] * 8B
#define CORE(sp)                                                              \
        const uint32_t* wp = (const uint32_t*)(bbase + s_idx[(sp)]);          \
        const uint32_t f = __funnelshift_r(wp[0], wp[1], rsh);                \
        const uint32_t Y = f ^ h1s ^ h2s;                                     \
        const uint32_t o01 = ((f & 12u) | ((Y >> 2) & 3u)) << 3;              \
        const uint32_t o23 = (((f >> 2) & 12u) | ((Y >> 4) & 3u)) << 3;       \
        const unsigned long long c01 = *(const unsigned long long*)(lutb + o01);\
        const unsigned long long c23 = *(const unsigned long long*)(lutb + o23);\
        FMA2(a01, a01, G2, c01);                                              \
        FMA2(a23, a23, G2, c23);                                              \
        h2s = h1s << 1;                                                       \
        h1s = f << 1;

    // u-only core for t = 0,1 (reference zeroes the shifted-history rows)
#define CORE0(sp)                                                             \
        const uint32_t* wp = (const uint32_t*)(bbase + s_idx[(sp)]);          \
        const uint32_t f = __funnelshift_r(wp[0], wp[1], rsh);                \
        const uint32_t u0 = ((f << 29) & 0x80000000u) | 0x3E99999Au;          \
        const uint32_t u1 = ((f << 28) & 0x80000000u) | 0x3E99999Au;          \
        const uint32_t u2 = ((f << 27) & 0x80000000u) | 0x3E99999Au;          \
        const uint32_t u3 = ((f << 26) & 0x80000000u) | 0x3E99999Au;          \
        FMA2(a01, a01, G2, pk2(u0, u1));                                      \
        FMA2(a23, a23, G2, pk2(u2, u3));                                      \
        h2s = h1s << 1;                                                       \
        h1s = f << 1;

#define EMIT(s)                                                               \
        const unsigned long long iv = s_inv2[(s)];                            \
        unsigned long long o01v, o23v;                                        \
        MUL2(o01v, a01, iv);                                                  \
        MUL2(o23v, a23, iv);                                                  \
        asm volatile("st.global.v2.b64 [%0], {%1, %2};"                       \
                     :: "l"(op), "l"(o01v), "l"(o23v) : "memory");            \
        op += DDIM;

    if (chunk == 0) {
        { CORE0(2) EMIT(0) }
        { CORE0(3) EMIT(1) }
#pragma unroll 8
        for (int s = 2; s < CLEN; s++) { CORE(s + 2) EMIT(s) }
    } else {
        int w = 0;
        if (chunk == 1) {            // exact: starts at t=0, zero trigram t=0,1
            { CORE0(2) }
            { CORE0(3) }
            w = 2;
        }
#pragma unroll 8
        for (; w < nwarm; w++) { CORE(w + 2) }
#pragma unroll 8
        for (int s = 0; s < CLEN; s++) { CORE(nwarm + s + 2) EMIT(s) }
    }
#undef CORE
#undef CORE0
#undef EMIT
}

extern "C" void kernel_launch(void* const* d_in, const int* in_sizes, int n_in,
                              void* d_out, int out_size)
{
    const float* cb  = (const float*)d_in[0];   // (256, 4096) f32 bipolar
    const int*   idx = (const int*)d_in[1];     // (8, 2048) i32
    float*       out = (float*)d_out;           // (8, 2048, 4096) f32

    dim3 pgrid(256, 4);
    pack_kernel<<<pgrid, NTHREADS>>>(cb);

    dim3 grid(NDG, NCHUNK, NB);                 // 8 x 16 x 8 = 1024 blocks
    scan_kernel<<<grid, NTHREADS>>>(idx, out);
}

// round 11
// speedup vs baseline: 1.6327x; 1.0114x over previous
#include <cuda_runtime.h>
#include <cstdint>
#include <cmath>

// HDCProcessor: bit-domain exponential-decay scan, single fused kernel.
// R11: paired steps (int2 idx load, LDS.128 inv pair), inv=0.05 constant for
//      chunks >= 3 (exact in fp32 for t >= 337), WUP 144 -> 128.
//   hdc[t,d] = 0.3*s(t,d) + 0.7*s(t,d)*s(t-1,d-1)*s(t-2,d-2)  (signs, rolls mod D)
//   acc_t = 0.95*acc_{t-1} + hdc_t ;  out[t] = acc_t * (1-g)/(1-g^{t+1})
// c in {+-1.0, +-0.4}: smem LUT[f1 f0 y1 y0] = {c_j, c_j+1}, broadcast LDS.
// Chunks 0,1 exact (start at t=0); chunks >=2 use a 128-step warmup
// (truncation ~3.5e-4 rel by measured geometric scaling; gate 1e-3).

#define DDIM     4096
#define NB       8
#define NT       2048
#define NCHUNK   16
#define CLEN     128
#define WUP      128
#define NTHREADS 128
#define NDG      8                 // 4096 dims / (128 thr * 4 dims)
#define ROWW     17                // words per staged row: 1 halo + 16 slice
#define RWORDS   (256 * ROWW)      // 4352
#define ROWB     (ROWW * 4)
#define SIDXN    (CLEN + WUP + 2)  // 258

__device__ uint32_t g_bitsx[NDG * RWORDS];   // per-dg pre-halo'd packed rows
__device__ float    g_inv[NT];               // (1-g)/(1-g^{t+1})

// ---- packed f32x2 helpers ----
__device__ __forceinline__ unsigned long long pk2(uint32_t lo, uint32_t hi) {
    unsigned long long r;
    asm("mov.b64 %0, {%1, %2};" : "=l"(r) : "r"(lo), "r"(hi));
    return r;
}
#define FMA2(d, a, b, c) \
    asm("fma.rn.f32x2 %0, %1, %2, %3;" : "=l"(d) : "l"(a), "l"(b), "l"(c))
#define MUL2(d, a, b) \
    asm("mul.rn.f32x2 %0, %1, %2;" : "=l"(d) : "l"(a), "l"(b))
#define G2    0x3F7333333F733333ull   // {0.95f, 0.95f}
#define INV05 0x3D4CCCCD3D4CCCCDull   // {0.05f, 0.05f}

// ---- pack: sign bits of the bipolar codebook, expanded per d-group ----
__global__ void pack_kernel(const float* __restrict__ cb) {
    const int row  = blockIdx.x;
    const int lane = threadIdx.x & 31;
    const int wq   = (blockIdx.y << 2) + (threadIdx.x >> 5);  // word quarter 0..15
    for (int k = 0; k < 8; k++) {
        int gw = wq * 8 + k;
        float v = cb[row * DDIM + gw * 32 + lane];
        unsigned m = __ballot_sync(0xffffffffu, v < 0.0f);
        if (lane == 0) {
            g_bitsx[(gw >> 4) * RWORDS + row * ROWW + (gw & 15) + 1] = m;
            int gwn = (gw + 1) & 127;               // this word is the halo of
            if ((gwn & 15) == 0)                    // the next d-group (mod wrap)
                g_bitsx[(gwn >> 4) * RWORDS + row * ROWW] = m;
        }
    }
    if (blockIdx.y == 0) {
        int gid = blockIdx.x * NTHREADS + threadIdx.x;
        if (gid < NT)
            g_inv[gid] = (float)(0.05 / (1.0 - pow(0.95, (double)(gid + 1))));
    }
}

// ---- fused scan ----
__global__ void __launch_bounds__(NTHREADS)
scan_kernel(const int* __restrict__ idx, float* __restrict__ out)
{
    const int dg    = blockIdx.x;
    const int chunk = blockIdx.y;
    const int b     = blockIdx.z;
    const int t0    = chunk * CLEN;
    const int tid   = threadIdx.x;

    __shared__ uint32_t s_bits[RWORDS + 4];
    __shared__ int      s_idx[SIDXN + 2];                // row byte offsets
    __shared__ unsigned long long s_inv2[CLEN];          // packed {inv, inv}
    __shared__ unsigned long long s_lut[16];             // packed {c_j, c_j+1}

    // c LUT: index [f1 f0 y1 y0]; c = 0.3*(f?-1:+1) + 0.7*(y?-1:+1)
    if (tid < 16) {
        float c0 = ((tid & 4) ? -0.3f : 0.3f) + ((tid & 1) ? -0.7f : 0.7f);
        float c1 = ((tid & 8) ? -0.3f : 0.3f) + ((tid & 2) ? -0.7f : 0.7f);
        s_lut[tid] = pk2(__float_as_uint(c0), __float_as_uint(c1));
    }
    // stage packed codebook slice (contiguous uint4 copy, L2-resident source)
    {
        const uint4* src = (const uint4*)(g_bitsx + dg * RWORDS);
        uint4*       dst = (uint4*)s_bits;
        for (int k = tid; k < RWORDS / 4; k += NTHREADS) dst[k] = src[k];
    }
    const int nwarm = chunk ? WUP : 0;     // WUP == CLEN: uniform for chunks >= 1
    const int ts    = t0 - nwarm;          // first scanned timestep
    for (int k = tid; k < SIDXN; k += NTHREADS) {
        int t = ts - 2 + k;                // tail entries past nsteps are unused
        s_idx[k] = ((t >= 0 && t < NT) ? idx[b * NT + t] : 0) * ROWB;
    }
    if (chunk < 3) {                       // chunks >= 3: inv == 0.05f exactly
        for (int k = tid; k < CLEN; k += NTHREADS) {
            float v = g_inv[t0 + k];
            s_inv2[k] = pk2(__float_as_uint(v), __float_as_uint(v));
        }
    }
    __syncthreads();

    // bit field: global dim (dg*512 + m) lives at staged-row bit (32 + m);
    // this thread needs dims d-2 .. d+3 => bits starting at p = 30 + 4*tid.
    // Both f (cur) and Y (trigram) carry dim j's sign at bit (2+j).
    const int p   = 30 + 4 * tid;
    const int q   = p >> 5;
    const int rsh = p & 31;
    const char* bbase = (const char*)(s_bits + q);
    const char* lutb  = (const char*)s_lut;

    uint32_t h1s = 0, h2s = 0;   // histories pre-shifted: f_{t-1}<<1, f_{t-2}<<2
    if (ts >= 2) {               // real history (chunk >= 2)
        const uint32_t* w1 = (const uint32_t*)(bbase + s_idx[1]);
        const uint32_t* w2 = (const uint32_t*)(bbase + s_idx[0]);
        h1s = __funnelshift_r(w1[0], w1[1], rsh) << 1;
        h2s = __funnelshift_r(w2[0], w2[1], rsh) << 2;
    }

    unsigned long long a01 = 0ull, a23 = 0ull;   // packed fp32 accumulators
    float* op = out + ((size_t)b * NT + t0) * DDIM + dg * 512 + 4 * tid;

    // one LUT step body (f given), updates accs only
#define LSTEP(F, H1, H2)                                                      \
        const uint32_t Y_ = (F) ^ (H1) ^ (H2);                                \
        const uint32_t o01_ = (((F) & 12u) | ((Y_ >> 2) & 3u)) << 3;          \
        const uint32_t o23_ = ((((F) >> 2) & 12u) | ((Y_ >> 4) & 3u)) << 3;   \
        FMA2(a01, a01, G2, *(const unsigned long long*)(lutb + o01_));        \
        FMA2(a23, a23, G2, *(const unsigned long long*)(lutb + o23_));

#define EMITV(IV)                                                             \
        unsigned long long o01v, o23v;                                        \
        MUL2(o01v, a01, (IV));                                                \
        MUL2(o23v, a23, (IV));                                                \
        asm volatile("st.global.v2.b64 [%0], {%1, %2};"                       \
                     :: "l"(op), "l"(o01v), "l"(o23v) : "memory");            \
        op += DDIM;

    // paired core: sp even; E0/E1 run after each step's acc update
#define CORE2(sp, E0, E1)                                                     \
    {                                                                         \
        const int2 ofs = *(const int2*)(s_idx + (sp));                        \
        const uint32_t* wpA = (const uint32_t*)(bbase + ofs.x);               \
        const uint32_t fA = __funnelshift_r(wpA[0], wpA[1], rsh);             \
        const uint32_t* wpB = (const uint32_t*)(bbase + ofs.y);               \
        const uint32_t fB = __funnelshift_r(wpB[0], wpB[1], rsh);             \
        { LSTEP(fA, h1s, h2s) }                                               \
        E0                                                                    \
        { LSTEP(fB, fA << 1, h1s << 1) }                                      \
        E1                                                                    \
        h2s = fA << 2;                                                        \
        h1s = fB << 1;                                                        \
    }

    // u-only single step for t = 0,1 (reference zeroes shifted-history rows)
#define CORE0(sp)                                                             \
    {                                                                         \
        const uint32_t* wp = (const uint32_t*)(bbase + s_idx[(sp)]);          \
        const uint32_t f = __funnelshift_r(wp[0], wp[1], rsh);                \
        const uint32_t u0 = ((f << 29) & 0x80000000u) | 0x3E99999Au;          \
        const uint32_t u1 = ((f << 28) & 0x80000000u) | 0x3E99999Au;          \
        const uint32_t u2 = ((f << 27) & 0x80000000u) | 0x3E99999Au;          \
        const uint32_t u3 = ((f << 26) & 0x80000000u) | 0x3E99999Au;          \
        FMA2(a01, a01, G2, pk2(u0, u1));                                      \
        FMA2(a23, a23, G2, pk2(u2, u3));                                      \
        h2s = h1s << 1;                                                       \
        h1s = f << 1;                                                         \
    }

    if (chunk == 0) {
        { CORE0(2) EMITV(s_inv2[0]) }
        { CORE0(3) EMITV(s_inv2[1]) }
#pragma unroll 8
        for (int s = 2; s < CLEN; s += 2) {
            const unsigned long long* ivp = &s_inv2[s];
            CORE2(s + 2, { EMITV(ivp[0]) }, { EMITV(ivp[1]) })
        }
    } else {
        // ---- warmup: 128 store-free steps ----
        int w = 0;
        if (chunk == 1) { CORE0(2) CORE0(3) w = 2; }
#pragma unroll 8
        for (; w < WUP; w += 2) { CORE2(w + 2, {}, {}) }
        // ---- store phase ----
        if (chunk < 3) {
#pragma unroll 8
            for (int s = 0; s < CLEN; s += 2) {
                const unsigned long long* ivp = &s_inv2[s];
                CORE2(WUP + s + 2, { EMITV(ivp[0]) }, { EMITV(ivp[1]) })
            }
        } else {       // t >= 384: (1-g)/(1-g^(t+1)) == 0.05f exactly in fp32
#pragma unroll 8
            for (int s = 0; s < CLEN; s += 2) {
                CORE2(WUP + s + 2, { EMITV(INV05) }, { EMITV(INV05) })
            }
        }
    }
#undef LSTEP
#undef EMITV
#undef CORE2
#undef CORE0
}

extern "C" void kernel_launch(void* const* d_in, const int* in_sizes, int n_in,
                              void* d_out, int out_size)
{
    const float* cb  = (const float*)d_in[0];   // (256, 4096) f32 bipolar
    const int*   idx = (const int*)d_in[1];     // (8, 2048) i32
    float*       out = (float*)d_out;           // (8, 2048, 4096) f32

    dim3 pgrid(256, 4);
    pack_kernel<<<pgrid, NTHREADS>>>(cb);

    dim3 grid(NDG, NCHUNK, NB);                 // 8 x 16 x 8 = 1024 blocks
    scan_kernel<<<grid, NTHREADS>>>(idx, out);
}